// round 1
// baseline (speedup 1.0000x reference)
#include <cuda_runtime.h>
#include <math.h>
#include <stddef.h>

#define NR 2048
#define DD 2048
#define NCLS 9
#define NBB 36

// ---- scratch (device globals: allocation-free rule) ----
__device__ float g_A[NR * DD];       // feat / x3
__device__ float g_B[NR * DD];       // x2
__device__ float g_M[NR * NR];       // cosine matrix
__device__ float g_T[NR * DD];       // mat@x / softmax result
__device__ float g_norms[NR];

// =====================================================================
// AvgPool2d(7,7) over [N, D, 7, 7] -> [N, D]; shared staging for
// LDG.128-aligned reads (49-float rows are not 16B aligned per-row).
// =====================================================================
__global__ void avgpool_kernel(const float* __restrict__ x, float* __restrict__ out) {
    __shared__ float s[128 * 49];
    size_t block0 = (size_t)blockIdx.x * 128;
    const float4* src = reinterpret_cast<const float4*>(x + block0 * 49);
    float4* dst = reinterpret_cast<float4*>(s);
    for (int i = threadIdx.x; i < 128 * 49 / 4; i += 256) dst[i] = src[i];
    __syncthreads();
    if (threadIdx.x < 128) {
        float sum = 0.f;
        #pragma unroll
        for (int k = 0; k < 49; k++) sum += s[threadIdx.x * 49 + k];
        out[block0 + threadIdx.x] = sum * (1.f / 49.f);
    }
}

// =====================================================================
// Row L2 norms: norms[i] = sqrt(sum_d f[i,d]^2)
// =====================================================================
__global__ void rownorm_kernel(const float* __restrict__ f, float* __restrict__ norms) {
    __shared__ float red[256];
    int row = blockIdx.x, t = threadIdx.x;
    const float4* p = reinterpret_cast<const float4*>(f + (size_t)row * DD);
    float s = 0.f;
    #pragma unroll
    for (int i = 0; i < 2; i++) {
        float4 v = p[t + i * 256];
        s += v.x * v.x + v.y * v.y + v.z * v.z + v.w * v.w;
    }
    red[t] = s;
    __syncthreads();
    for (int o = 128; o; o >>= 1) {
        if (t < o) red[t] += red[t + o];
        __syncthreads();
    }
    if (t == 0) norms[row] = sqrtf(red[0]);
}

// =====================================================================
// Row softmax in place over [NR, NR]
// =====================================================================
__global__ void softmax_kernel(float* __restrict__ y) {
    __shared__ float red[256];
    int row = blockIdx.x, t = threadIdx.x;
    float* p = y + (size_t)row * NR;
    float v[8];
    float mx = -1e30f;
    #pragma unroll
    for (int i = 0; i < 8; i++) {
        v[i] = p[t + i * 256];
        mx = fmaxf(mx, v[i]);
    }
    red[t] = mx;
    __syncthreads();
    for (int o = 128; o; o >>= 1) {
        if (t < o) red[t] = fmaxf(red[t], red[t + o]);
        __syncthreads();
    }
    mx = red[0];
    __syncthreads();
    float s = 0.f;
    #pragma unroll
    for (int i = 0; i < 8; i++) {
        v[i] = __expf(v[i] - mx);
        s += v[i];
    }
    red[t] = s;
    __syncthreads();
    for (int o = 128; o; o >>= 1) {
        if (t < o) red[t] += red[t + o];
        __syncthreads();
    }
    float inv = 1.f / red[0];
    #pragma unroll
    for (int i = 0; i < 8; i++) p[t + i * 256] = v[i] * inv;
}

// =====================================================================
// 2048x2048x2048 SGEMM, 128x128x16 tile, 256 threads, 8x8 microtile.
//   BT = true : C = A * B^T   (A [M,K] rm, B [N,K] rm)  -- NT
//   BT = false: C = A * B     (A [M,K] rm, B [K,N] rm)  -- NN
// EPI: 0 plain, 1 cosine (/= max(norm_r*norm_c, eps)), 2 (+bias[c]+res[r,c])
// =====================================================================
template <int EPI, bool BT>
__global__ __launch_bounds__(256, 2)
void gemm2048(const float* __restrict__ A, const float* __restrict__ B,
              float* __restrict__ C,
              const float* __restrict__ norms,
              const float* __restrict__ bias,
              const float* __restrict__ res) {
    const int K = 2048, LD = 2048;
    __shared__ float As[16][128];
    __shared__ float Bs[16][128];

    int tid = threadIdx.x;
    int bm0 = blockIdx.y * 128;
    int bn0 = blockIdx.x * 128;
    int tx = tid & 15;
    int ty = tid >> 4;

    float acc[8][8];
    #pragma unroll
    for (int i = 0; i < 8; i++)
        #pragma unroll
        for (int j = 0; j < 8; j++) acc[i][j] = 0.f;

    int ar = tid >> 2;           // 0..63
    int ac = (tid & 3) << 2;     // 0,4,8,12
    int bk = tid >> 5;           // 0..7   (NN path)
    int bn = (tid & 31) << 2;    // 0..124 (NN path)

    for (int k0 = 0; k0 < K; k0 += 16) {
        // ---- A tile: As[k][m] ----
        {
            const float* Ap = A + (size_t)(bm0 + ar) * LD + k0 + ac;
            float4 a0 = *(const float4*)Ap;
            float4 a1 = *(const float4*)(Ap + (size_t)64 * LD);
            As[ac + 0][ar] = a0.x; As[ac + 1][ar] = a0.y;
            As[ac + 2][ar] = a0.z; As[ac + 3][ar] = a0.w;
            As[ac + 0][ar + 64] = a1.x; As[ac + 1][ar + 64] = a1.y;
            As[ac + 2][ar + 64] = a1.z; As[ac + 3][ar + 64] = a1.w;
        }
        // ---- B tile: Bs[k][n] ----
        if (BT) {
            const float* Bp = B + (size_t)(bn0 + ar) * LD + k0 + ac;
            float4 b0 = *(const float4*)Bp;
            float4 b1 = *(const float4*)(Bp + (size_t)64 * LD);
            Bs[ac + 0][ar] = b0.x; Bs[ac + 1][ar] = b0.y;
            Bs[ac + 2][ar] = b0.z; Bs[ac + 3][ar] = b0.w;
            Bs[ac + 0][ar + 64] = b1.x; Bs[ac + 1][ar + 64] = b1.y;
            Bs[ac + 2][ar + 64] = b1.z; Bs[ac + 3][ar + 64] = b1.w;
        } else {
            const float* Bp = B + (size_t)(k0 + bk) * LD + bn0 + bn;
            float4 b0 = *(const float4*)Bp;
            float4 b1 = *(const float4*)(Bp + (size_t)8 * LD);
            *(float4*)&Bs[bk][bn] = b0;
            *(float4*)&Bs[bk + 8][bn] = b1;
        }
        __syncthreads();

        #pragma unroll
        for (int kk = 0; kk < 16; kk++) {
            float4 a0 = *(const float4*)&As[kk][ty * 4];
            float4 a1 = *(const float4*)&As[kk][ty * 4 + 64];
            float4 b0 = *(const float4*)&Bs[kk][tx * 4];
            float4 b1 = *(const float4*)&Bs[kk][tx * 4 + 64];
            float av[8] = {a0.x, a0.y, a0.z, a0.w, a1.x, a1.y, a1.z, a1.w};
            float bv[8] = {b0.x, b0.y, b0.z, b0.w, b1.x, b1.y, b1.z, b1.w};
            #pragma unroll
            for (int i = 0; i < 8; i++)
                #pragma unroll
                for (int j = 0; j < 8; j++) acc[i][j] += av[i] * bv[j];
        }
        __syncthreads();
    }

    // ---- epilogue ----
    #pragma unroll
    for (int i = 0; i < 8; i++) {
        int r = bm0 + ty * 4 + (i & 3) + (i >> 2) * 64;
        float* crow = C + (size_t)r * 2048;
        float nr_i = (EPI == 1) ? norms[r] : 0.f;
        #pragma unroll
        for (int jh = 0; jh < 2; jh++) {
            int c0 = bn0 + tx * 4 + jh * 64;
            float4 v;
            v.x = acc[i][jh * 4 + 0];
            v.y = acc[i][jh * 4 + 1];
            v.z = acc[i][jh * 4 + 2];
            v.w = acc[i][jh * 4 + 3];
            if (EPI == 1) {
                float4 nc = *(const float4*)&norms[c0];
                v.x /= fmaxf(nr_i * nc.x, 1e-8f);
                v.y /= fmaxf(nr_i * nc.y, 1e-8f);
                v.z /= fmaxf(nr_i * nc.z, 1e-8f);
                v.w /= fmaxf(nr_i * nc.w, 1e-8f);
            } else if (EPI == 2) {
                float4 bi = *(const float4*)&bias[c0];
                float4 rs = *(const float4*)&res[(size_t)r * 2048 + c0];
                v.x += bi.x + rs.x;
                v.y += bi.y + rs.y;
                v.z += bi.z + rs.z;
                v.w += bi.w + rs.w;
            }
            *(float4*)&crow[c0] = v;
        }
    }
}

// =====================================================================
// Head: cls = x @ Wc^T + bc  [2048,9]; bbox = x @ Wb^T + bb [2048,36].
// One warp per output element, warp-strided float4 dot + shfl reduce.
// Output layout: cls (2048*9) then bbox (2048*36).
// =====================================================================
__global__ void head_kernel(const float* __restrict__ x,
                            const float* __restrict__ Wc, const float* __restrict__ bc,
                            const float* __restrict__ Wb, const float* __restrict__ bb,
                            float* __restrict__ out) {
    int gw = (int)((blockIdx.x * blockDim.x + threadIdx.x) >> 5);
    int lane = threadIdx.x & 31;
    if (gw >= NR * 45) return;
    int i = gw / 45;
    int j = gw - i * 45;
    const float* w = (j < NCLS) ? (Wc + (size_t)j * DD) : (Wb + (size_t)(j - NCLS) * DD);
    const float4* xr = (const float4*)(x + (size_t)i * DD);
    const float4* w4 = (const float4*)w;
    float s = 0.f;
    #pragma unroll 4
    for (int k = lane; k < DD / 4; k += 32) {
        float4 a = xr[k], b = w4[k];
        s += a.x * b.x + a.y * b.y + a.z * b.z + a.w * b.w;
    }
    #pragma unroll
    for (int o = 16; o; o >>= 1) s += __shfl_xor_sync(0xffffffffu, s, o);
    if (lane == 0) {
        if (j < NCLS)
            out[(size_t)i * NCLS + j] = s + bc[j];
        else
            out[(size_t)NR * NCLS + (size_t)i * NBB + (j - NCLS)] = s + bb[j - NCLS];
    }
}

// =====================================================================
extern "C" void kernel_launch(void* const* d_in, const int* in_sizes, int n_in,
                              void* d_out, int out_size) {
    const float* x  = (const float*)d_in[0];
    const float* Wt = (const float*)d_in[1];
    const float* bt = (const float*)d_in[2];
    const float* Wr = (const float*)d_in[3];
    const float* br = (const float*)d_in[4];
    const float* Wc = (const float*)d_in[5];
    const float* bc = (const float*)d_in[6];
    const float* Wb = (const float*)d_in[7];
    const float* bb = (const float*)d_in[8];
    float* out = (float*)d_out;

    float *A, *B, *M, *T, *nrm;
    cudaGetSymbolAddress((void**)&A, g_A);
    cudaGetSymbolAddress((void**)&B, g_B);
    cudaGetSymbolAddress((void**)&M, g_M);
    cudaGetSymbolAddress((void**)&T, g_T);
    cudaGetSymbolAddress((void**)&nrm, g_norms);

    dim3 gg(16, 16);

    // feat = avgpool(x)
    avgpool_kernel<<<NR * DD / 128, 256>>>(x, A);

    // ---- layer 1 ----
    rownorm_kernel<<<NR, 256>>>(A, nrm);
    gemm2048<1, true><<<gg, 256>>>(A, A, M, nrm, nullptr, nullptr);   // cosine mat
    gemm2048<0, false><<<gg, 256>>>(M, A, T, nullptr, nullptr, nullptr); // mat @ x
    softmax_kernel<<<NR, 256>>>(T);
    gemm2048<2, true><<<gg, 256>>>(T, Wt, B, nullptr, bt, A);         // @Wt^T + bt + x

    // ---- layer 2 ----
    rownorm_kernel<<<NR, 256>>>(B, nrm);
    gemm2048<1, true><<<gg, 256>>>(B, B, M, nrm, nullptr, nullptr);
    gemm2048<0, false><<<gg, 256>>>(M, B, T, nullptr, nullptr, nullptr);
    softmax_kernel<<<NR, 256>>>(T);
    gemm2048<2, true><<<gg, 256>>>(T, Wr, A, nullptr, br, B);         // @Wr^T + br + x2

    // ---- heads ----
    head_kernel<<<(NR * 45) / 8, 256>>>(A, Wc, bc, Wb, bb, out);
}

// round 3
// speedup vs baseline: 2.7813x; 2.7813x over previous
#include <cuda_runtime.h>
#include <math.h>
#include <stddef.h>
#include <stdint.h>

#define NR 2048
#define DD 2048
#define NCLS 9
#define NBB 36

// ---- scratch (device globals: allocation-free rule) ----
__device__ float g_A[NR * DD];
__device__ float g_B[NR * DD];
__device__ float g_M[NR * NR];
__device__ float g_T[NR * DD];
__device__ float g_AT[NR * DD];   // transpose scratch; reused as head partials
__device__ float g_norms[NR];

// =====================================================================
// helpers
// =====================================================================
__device__ __forceinline__ uint32_t smem_u32(const void* p) {
    uint32_t a;
    asm("{ .reg .u64 t; cvta.to.shared.u64 t, %1; cvt.u32.u64 %0, t; }"
        : "=r"(a) : "l"(p));
    return a;
}
__device__ __forceinline__ uint32_t f2tf32(float f) {
    uint32_t u;
    asm("cvt.rna.tf32.f32 %0, %1;" : "=r"(u) : "f"(f));
    return u;
}
#define CP_ASYNC16(dst, src) \
    asm volatile("cp.async.ca.shared.global [%0], [%1], 16;" :: "r"(dst), "l"(src) : "memory")
#define CP_COMMIT() asm volatile("cp.async.commit_group;" ::: "memory")
#define CP_WAIT(n)  asm volatile("cp.async.wait_group %0;" :: "n"(n) : "memory")

__device__ __forceinline__ void mma_tf32(float* c, const uint32_t* a, const uint32_t* b) {
    asm volatile(
        "mma.sync.aligned.m16n8k8.row.col.f32.tf32.tf32.f32 "
        "{%0,%1,%2,%3}, {%4,%5,%6,%7}, {%8,%9}, {%0,%1,%2,%3};"
        : "+f"(c[0]), "+f"(c[1]), "+f"(c[2]), "+f"(c[3])
        : "r"(a[0]), "r"(a[1]), "r"(a[2]), "r"(a[3]), "r"(b[0]), "r"(b[1]));
}

// =====================================================================
// AvgPool2d(7,7): [N, D, 7, 7] -> [N, D]
// =====================================================================
__global__ void avgpool_kernel(const float* __restrict__ x, float* __restrict__ out) {
    __shared__ float s[128 * 49];
    size_t block0 = (size_t)blockIdx.x * 128;
    const float4* src = reinterpret_cast<const float4*>(x + block0 * 49);
    float4* dst = reinterpret_cast<float4*>(s);
    for (int i = threadIdx.x; i < 128 * 49 / 4; i += 256) dst[i] = src[i];
    __syncthreads();
    if (threadIdx.x < 128) {
        float sum = 0.f;
        #pragma unroll
        for (int k = 0; k < 49; k++) sum += s[threadIdx.x * 49 + k];
        out[block0 + threadIdx.x] = sum * (1.f / 49.f);
    }
}

// =====================================================================
// Row L2 norms
// =====================================================================
__global__ void rownorm_kernel(const float* __restrict__ f, float* __restrict__ norms) {
    __shared__ float red[256];
    int row = blockIdx.x, t = threadIdx.x;
    const float4* p = reinterpret_cast<const float4*>(f + (size_t)row * DD);
    float s = 0.f;
    #pragma unroll
    for (int i = 0; i < 2; i++) {
        float4 v = p[t + i * 256];
        s += v.x * v.x + v.y * v.y + v.z * v.z + v.w * v.w;
    }
    red[t] = s;
    __syncthreads();
    for (int o = 128; o; o >>= 1) {
        if (t < o) red[t] += red[t + o];
        __syncthreads();
    }
    if (t == 0) norms[row] = sqrtf(red[0]);
}

// =====================================================================
// Row softmax in place over [NR, NR]
// =====================================================================
__global__ void softmax_kernel(float* __restrict__ y) {
    __shared__ float red[256];
    int row = blockIdx.x, t = threadIdx.x;
    float* p = y + (size_t)row * NR;
    float v[8];
    float mx = -1e30f;
    #pragma unroll
    for (int i = 0; i < 8; i++) {
        v[i] = p[t + i * 256];
        mx = fmaxf(mx, v[i]);
    }
    red[t] = mx;
    __syncthreads();
    for (int o = 128; o; o >>= 1) {
        if (t < o) red[t] = fmaxf(red[t], red[t + o]);
        __syncthreads();
    }
    mx = red[0];
    __syncthreads();
    float s = 0.f;
    #pragma unroll
    for (int i = 0; i < 8; i++) {
        v[i] = __expf(v[i] - mx);
        s += v[i];
    }
    red[t] = s;
    __syncthreads();
    for (int o = 128; o; o >>= 1) {
        if (t < o) red[t] += red[t + o];
        __syncthreads();
    }
    float inv = 1.f / red[0];
    #pragma unroll
    for (int i = 0; i < 8; i++) p[t + i * 256] = v[i] * inv;
}

// =====================================================================
// 32x32 tiled transpose: out = in^T
// =====================================================================
__global__ void transpose_kernel(const float* __restrict__ in, float* __restrict__ out) {
    __shared__ float tile[32][33];
    int x = blockIdx.x * 32 + threadIdx.x;
    int y = blockIdx.y * 32 + threadIdx.y;
    #pragma unroll
    for (int j = 0; j < 32; j += 8)
        tile[threadIdx.y + j][threadIdx.x] = in[(size_t)(y + j) * DD + x];
    __syncthreads();
    x = blockIdx.y * 32 + threadIdx.x;
    y = blockIdx.x * 32 + threadIdx.y;
    #pragma unroll
    for (int j = 0; j < 32; j += 8)
        out[(size_t)(y + j) * DD + x] = tile[threadIdx.x][threadIdx.y + j];
}

// =====================================================================
// tf32 mma.sync NT GEMM: C[m,n] = sum_k A[m,k] * B[n,k]  (2048^3)
// 128x128 CTA tile, 256 thr (8 warps @ 32x64), BK=32, cp.async dbl-buf.
// SMEM rows padded to 36 floats -> conflict-free 32b fragment LDS.
// EPI: 0 plain | 1 cosine | 2 (+bias[c]+res[r,c])
// =====================================================================
#define SMSTRIDE 36
#define BUFF 9216   // floats per buffer (A 4608 + B 4608)

__device__ __forceinline__ void load_stage(uint32_t smbase, const float* A, const float* B,
                                           int bm0, int bn0, int k0, int buf, int t) {
    int row = t >> 3;
    int q = t & 7;
    uint32_t da = smbase + (uint32_t)(buf * BUFF + row * SMSTRIDE + q * 4) * 4u;
    uint32_t db = da + 4608u * 4u;
    const float* ga = A + (size_t)(bm0 + row) * DD + k0 + q * 4;
    const float* gb = B + (size_t)(bn0 + row) * DD + k0 + q * 4;
    #pragma unroll
    for (int p = 0; p < 4; p++) {
        CP_ASYNC16(da + (uint32_t)(p * 32 * SMSTRIDE * 4), ga + (size_t)p * 32 * DD);
        CP_ASYNC16(db + (uint32_t)(p * 32 * SMSTRIDE * 4), gb + (size_t)p * 32 * DD);
    }
}

template <int EPI>
__global__ __launch_bounds__(256, 2)
void gemm_mma(const float* __restrict__ A, const float* __restrict__ B,
              float* __restrict__ C,
              const float* __restrict__ norms,
              const float* __restrict__ bias,
              const float* __restrict__ res) {
    extern __shared__ float sm[];
    const int t = threadIdx.x;
    const int lane = t & 31, wid = t >> 5;
    const int wm = (wid & 3) * 32;
    const int wn = (wid >> 2) * 64;
    const int bm0 = blockIdx.y * 128;
    const int bn0 = blockIdx.x * 128;
    const uint32_t smbase = smem_u32(sm);

    float acc[2][8][4];
    #pragma unroll
    for (int i = 0; i < 2; i++)
        #pragma unroll
        for (int j = 0; j < 8; j++)
            #pragma unroll
            for (int q = 0; q < 4; q++) acc[i][j][q] = 0.f;

    load_stage(smbase, A, B, bm0, bn0, 0, 0, t);
    CP_COMMIT();

    const int rA = wm + (lane >> 2);
    const int cA = lane & 3;
    const int rB = wn + (lane >> 2);

    for (int s = 0; s < 64; s++) {
        if (s < 63) {
            load_stage(smbase, A, B, bm0, bn0, (s + 1) * 32, (s + 1) & 1, t);
            CP_COMMIT();
            CP_WAIT(1);
        } else {
            CP_WAIT(0);
        }
        __syncthreads();

        const float* As = sm + (s & 1) * BUFF;
        const float* Bs = As + 4608;
        #pragma unroll
        for (int kk = 0; kk < 4; kk++) {
            const int k = kk * 8;
            uint32_t a[2][4], b[8][2];
            #pragma unroll
            for (int mt = 0; mt < 2; mt++) {
                int base = (rA + mt * 16) * SMSTRIDE + k + cA;
                a[mt][0] = f2tf32(As[base]);
                a[mt][1] = f2tf32(As[base + 8 * SMSTRIDE]);
                a[mt][2] = f2tf32(As[base + 4]);
                a[mt][3] = f2tf32(As[base + 8 * SMSTRIDE + 4]);
            }
            #pragma unroll
            for (int nt = 0; nt < 8; nt++) {
                int base = (rB + nt * 8) * SMSTRIDE + k + cA;
                b[nt][0] = f2tf32(Bs[base]);
                b[nt][1] = f2tf32(Bs[base + 4]);
            }
            #pragma unroll
            for (int mt = 0; mt < 2; mt++)
                #pragma unroll
                for (int nt = 0; nt < 8; nt++)
                    mma_tf32(acc[mt][nt], a[mt], b[nt]);
        }
        __syncthreads();
    }

    // ---- epilogue: direct float2 stores ----
    #pragma unroll
    for (int mt = 0; mt < 2; mt++) {
        const int row0 = bm0 + wm + mt * 16 + (lane >> 2);
        #pragma unroll
        for (int nt = 0; nt < 8; nt++) {
            const int col0 = bn0 + wn + nt * 8 + (lane & 3) * 2;
            float v0 = acc[mt][nt][0], v1 = acc[mt][nt][1];
            float v2 = acc[mt][nt][2], v3 = acc[mt][nt][3];
            if (EPI == 1) {
                float nr0 = norms[row0], nr1 = norms[row0 + 8];
                float nc0 = norms[col0], nc1 = norms[col0 + 1];
                v0 /= fmaxf(nr0 * nc0, 1e-8f);
                v1 /= fmaxf(nr0 * nc1, 1e-8f);
                v2 /= fmaxf(nr1 * nc0, 1e-8f);
                v3 /= fmaxf(nr1 * nc1, 1e-8f);
            } else if (EPI == 2) {
                float b0 = bias[col0], b1 = bias[col0 + 1];
                const float2 r0 = *(const float2*)&res[(size_t)row0 * DD + col0];
                const float2 r1 = *(const float2*)&res[(size_t)(row0 + 8) * DD + col0];
                v0 += b0 + r0.x; v1 += b1 + r0.y;
                v2 += b0 + r1.x; v3 += b1 + r1.y;
            }
            float2 o0 = {v0, v1}, o1 = {v2, v3};
            *(float2*)&C[(size_t)row0 * DD + col0] = o0;
            *(float2*)&C[(size_t)(row0 + 8) * DD + col0] = o1;
        }
    }
}

// =====================================================================
// Head, split-K: part[ks][row][j] = sum_{k in ks} x[row,k]*W_all[j,k]
// grid (64 row-blocks, 8 k-splits), 256 thr. W_all = [Wc;Wb] (45x2048).
// =====================================================================
__global__ __launch_bounds__(256)
void head_partial(const float* __restrict__ x,
                  const float* __restrict__ Wc, const float* __restrict__ Wb,
                  float* __restrict__ part) {
    __shared__ float Wsm[48 * 64];   // rows 45..47 unused (never stored)
    __shared__ float xs[32 * 65];
    const int rb = blockIdx.x, ks = blockIdx.y;
    const int t = threadIdx.x;
    const int r = t & 31, jg = t >> 5;

    float acc[6] = {0.f, 0.f, 0.f, 0.f, 0.f, 0.f};

    for (int k0 = ks * 256; k0 < ks * 256 + 256; k0 += 64) {
        for (int i = t; i < 45 * 64; i += 256) {
            int j = i >> 6, k = i & 63;
            const float* w = (j < NCLS) ? (Wc + (size_t)j * DD)
                                        : (Wb + (size_t)(j - NCLS) * DD);
            Wsm[i] = w[k0 + k];
        }
        for (int i = t; i < 32 * 64; i += 256) {
            int rr = i >> 6, k = i & 63;
            xs[rr * 65 + k] = x[(size_t)(rb * 32 + rr) * DD + k0 + k];
        }
        __syncthreads();
        #pragma unroll 4
        for (int k = 0; k < 64; k++) {
            float xv = xs[r * 65 + k];
            #pragma unroll
            for (int u = 0; u < 6; u++) {
                int j = jg + 8 * u;
                if (j < 45) acc[u] += xv * Wsm[j * 64 + k];
            }
        }
        __syncthreads();
    }
    #pragma unroll
    for (int u = 0; u < 6; u++) {
        int j = jg + 8 * u;
        if (j < 45)
            part[((size_t)ks * NR + rb * 32 + r) * 45 + j] = acc[u];
    }
}

__global__ void head_reduce(const float* __restrict__ part,
                            const float* __restrict__ bc, const float* __restrict__ bb,
                            float* __restrict__ out) {
    int idx = blockIdx.x * 256 + threadIdx.x;
    if (idx >= NR * 45) return;
    int i = idx / 45, j = idx - i * 45;
    float s = 0.f;
    #pragma unroll
    for (int ks = 0; ks < 8; ks++) s += part[((size_t)ks * NR + i) * 45 + j];
    if (j < NCLS)
        out[(size_t)i * NCLS + j] = s + bc[j];
    else
        out[(size_t)NR * NCLS + (size_t)i * NBB + (j - NCLS)] = s + bb[j - NCLS];
}

// =====================================================================
extern "C" void kernel_launch(void* const* d_in, const int* in_sizes, int n_in,
                              void* d_out, int out_size) {
    const float* x  = (const float*)d_in[0];
    const float* Wt = (const float*)d_in[1];
    const float* bt = (const float*)d_in[2];
    const float* Wr = (const float*)d_in[3];
    const float* br = (const float*)d_in[4];
    const float* Wc = (const float*)d_in[5];
    const float* bc = (const float*)d_in[6];
    const float* Wb = (const float*)d_in[7];
    const float* bb = (const float*)d_in[8];
    float* out = (float*)d_out;

    float *A, *B, *M, *T, *AT, *nrm;
    cudaGetSymbolAddress((void**)&A, g_A);
    cudaGetSymbolAddress((void**)&B, g_B);
    cudaGetSymbolAddress((void**)&M, g_M);
    cudaGetSymbolAddress((void**)&T, g_T);
    cudaGetSymbolAddress((void**)&AT, g_AT);
    cudaGetSymbolAddress((void**)&nrm, g_norms);

    const int SMEM = 2 * BUFF * 4;   // 73728 B
    cudaFuncSetAttribute(gemm_mma<0>, cudaFuncAttributeMaxDynamicSharedMemorySize, SMEM);
    cudaFuncSetAttribute(gemm_mma<1>, cudaFuncAttributeMaxDynamicSharedMemorySize, SMEM);
    cudaFuncSetAttribute(gemm_mma<2>, cudaFuncAttributeMaxDynamicSharedMemorySize, SMEM);

    dim3 gg(16, 16);

    avgpool_kernel<<<NR * DD / 128, 256>>>(x, A);

    // ---- layer 1 ----
    rownorm_kernel<<<NR, 256>>>(A, nrm);
    gemm_mma<1><<<gg, 256, SMEM>>>(A, A, M, nrm, nullptr, nullptr);      // cosine
    transpose_kernel<<<dim3(64, 64), dim3(32, 8)>>>(A, AT);
    gemm_mma<0><<<gg, 256, SMEM>>>(M, AT, T, nullptr, nullptr, nullptr); // mat @ x
    softmax_kernel<<<NR, 256>>>(T);
    gemm_mma<2><<<gg, 256, SMEM>>>(T, Wt, B, nullptr, bt, A);            // @Wt^T+bt+x

    // ---- layer 2 ----
    rownorm_kernel<<<NR, 256>>>(B, nrm);
    gemm_mma<1><<<gg, 256, SMEM>>>(B, B, M, nrm, nullptr, nullptr);
    transpose_kernel<<<dim3(64, 64), dim3(32, 8)>>>(B, AT);
    gemm_mma<0><<<gg, 256, SMEM>>>(M, AT, T, nullptr, nullptr, nullptr);
    softmax_kernel<<<NR, 256>>>(T);
    gemm_mma<2><<<gg, 256, SMEM>>>(T, Wr, A, nullptr, br, B);            // @Wr^T+br+x2

    // ---- heads (split-K partials into AT scratch, then reduce) ----
    head_partial<<<dim3(64, 8), 256>>>(A, Wc, Wb, AT);
    head_reduce<<<(NR * 45 + 255) / 256, 256>>>(AT, bc, bb, out);
}

// round 4
// speedup vs baseline: 3.8735x; 1.3927x over previous
#include <cuda_runtime.h>
#include <math.h>
#include <stddef.h>
#include <stdint.h>

#define NR 2048
#define DD 2048
#define NCLS 9
#define NBB 36

// ---- scratch (device globals: allocation-free rule) ----
__device__ float g_A[NR * DD];
__device__ float g_B[NR * DD];
__device__ float g_M[NR * NR];
__device__ float g_T[NR * DD];
__device__ float g_AT[NR * DD];   // transpose scratch; reused as head partials
__device__ float g_N[NR * DD];    // row-normalized features

// =====================================================================
// helpers
// =====================================================================
__device__ __forceinline__ uint32_t smem_u32(const void* p) {
    uint32_t a;
    asm("{ .reg .u64 t; cvta.to.shared.u64 t, %1; cvt.u32.u64 %0, t; }"
        : "=r"(a) : "l"(p));
    return a;
}
// pack two f32 -> bf16x2 (lo = v.x (lower k), hi = v.y)
__device__ __forceinline__ uint32_t pack2(float2 v) {
    uint32_t r;
    asm("cvt.rn.bf16x2.f32 %0, %1, %2;" : "=r"(r) : "f"(v.y), "f"(v.x));
    return r;
}
#define CP_ASYNC16(dst, src) \
    asm volatile("cp.async.ca.shared.global [%0], [%1], 16;" :: "r"(dst), "l"(src) : "memory")
#define CP_COMMIT() asm volatile("cp.async.commit_group;" ::: "memory")
#define CP_WAIT(n)  asm volatile("cp.async.wait_group %0;" :: "n"(n) : "memory")

__device__ __forceinline__ void mma_bf16(float* c, const uint32_t* a, const uint32_t* b) {
    asm volatile(
        "mma.sync.aligned.m16n8k16.row.col.f32.bf16.bf16.f32 "
        "{%0,%1,%2,%3}, {%4,%5,%6,%7}, {%8,%9}, {%0,%1,%2,%3};"
        : "+f"(c[0]), "+f"(c[1]), "+f"(c[2]), "+f"(c[3])
        : "r"(a[0]), "r"(a[1]), "r"(a[2]), "r"(a[3]), "r"(b[0]), "r"(b[1]));
}

// =====================================================================
// AvgPool2d(7,7): [N, D, 7, 7] -> [N, D]
// =====================================================================
__global__ void avgpool_kernel(const float* __restrict__ x, float* __restrict__ out) {
    __shared__ float s[128 * 49];
    size_t block0 = (size_t)blockIdx.x * 128;
    const float4* src = reinterpret_cast<const float4*>(x + block0 * 49);
    float4* dst = reinterpret_cast<float4*>(s);
    for (int i = threadIdx.x; i < 128 * 49 / 4; i += 256) dst[i] = src[i];
    __syncthreads();
    if (threadIdx.x < 128) {
        float sum = 0.f;
        #pragma unroll
        for (int k = 0; k < 49; k++) sum += s[threadIdx.x * 49 + k];
        out[block0 + threadIdx.x] = sum * (1.f / 49.f);
    }
}

// =====================================================================
// Row L2-normalize: xn[i,:] = x[i,:] / max(||x[i,:]||, 1e-8)
// =====================================================================
__global__ void normalize_kernel(const float* __restrict__ f, float* __restrict__ fn) {
    __shared__ float red[256];
    int row = blockIdx.x, t = threadIdx.x;
    const float4* p = reinterpret_cast<const float4*>(f + (size_t)row * DD);
    float4 v0 = p[t], v1 = p[t + 256];
    float s = v0.x * v0.x + v0.y * v0.y + v0.z * v0.z + v0.w * v0.w
            + v1.x * v1.x + v1.y * v1.y + v1.z * v1.z + v1.w * v1.w;
    red[t] = s;
    __syncthreads();
    for (int o = 128; o; o >>= 1) {
        if (t < o) red[t] += red[t + o];
        __syncthreads();
    }
    float inv = 1.f / fmaxf(sqrtf(red[0]), 1e-8f);
    float4* q = reinterpret_cast<float4*>(fn + (size_t)row * DD);
    v0.x *= inv; v0.y *= inv; v0.z *= inv; v0.w *= inv;
    v1.x *= inv; v1.y *= inv; v1.z *= inv; v1.w *= inv;
    q[t] = v0; q[t + 256] = v1;
}

// =====================================================================
// Row softmax in place over [NR, 2048]
// =====================================================================
__global__ void softmax_kernel(float* __restrict__ y) {
    __shared__ float red[256];
    int row = blockIdx.x, t = threadIdx.x;
    float* p = y + (size_t)row * NR;
    float v[8];
    float mx = -1e30f;
    #pragma unroll
    for (int i = 0; i < 8; i++) {
        v[i] = p[t + i * 256];
        mx = fmaxf(mx, v[i]);
    }
    red[t] = mx;
    __syncthreads();
    for (int o = 128; o; o >>= 1) {
        if (t < o) red[t] = fmaxf(red[t], red[t + o]);
        __syncthreads();
    }
    mx = red[0];
    __syncthreads();
    float s = 0.f;
    #pragma unroll
    for (int i = 0; i < 8; i++) {
        v[i] = __expf(v[i] - mx);
        s += v[i];
    }
    red[t] = s;
    __syncthreads();
    for (int o = 128; o; o >>= 1) {
        if (t < o) red[t] += red[t + o];
        __syncthreads();
    }
    float inv = 1.f / red[0];
    #pragma unroll
    for (int i = 0; i < 8; i++) p[t + i * 256] = v[i] * inv;
}

// =====================================================================
// 32x32 tiled transpose: out = in^T
// =====================================================================
__global__ void transpose_kernel(const float* __restrict__ in, float* __restrict__ out) {
    __shared__ float tile[32][33];
    int x = blockIdx.x * 32 + threadIdx.x;
    int y = blockIdx.y * 32 + threadIdx.y;
    #pragma unroll
    for (int j = 0; j < 32; j += 8)
        tile[threadIdx.y + j][threadIdx.x] = in[(size_t)(y + j) * DD + x];
    __syncthreads();
    x = blockIdx.y * 32 + threadIdx.x;
    y = blockIdx.x * 32 + threadIdx.y;
    #pragma unroll
    for (int j = 0; j < 32; j += 8)
        out[(size_t)(y + j) * DD + x] = tile[threadIdx.x][threadIdx.y + j];
}

// =====================================================================
// bf16 mma.sync NT GEMM: C[m,n] = sum_k A[m,k] * B[n,k]  (2048^3)
// 128x128 CTA tile, 256 thr (8 warps @ 32x64), BK=32, cp.async dbl-buf.
// fp32 smem (stride 40 -> conflict-free LDS.64), cvt to bf16x2 at frag load.
// EPI: 0 plain | 2 (+bias[c]+res[r,c]).  SYM: triangular grid, mirror writes.
// =====================================================================
#define SMSTRIDE 40
#define TILEW (128 * SMSTRIDE)   // 5120 floats per tile
#define BUFW (2 * TILEW)         // A+B per buffer

__device__ __forceinline__ void load_stage(uint32_t smbase, const float* A, const float* B,
                                           int bm0, int bn0, int k0, int buf, int t) {
    int row = t >> 3;
    int q = t & 7;
    uint32_t da = smbase + (uint32_t)(buf * BUFW + row * SMSTRIDE + q * 4) * 4u;
    uint32_t db = da + (uint32_t)TILEW * 4u;
    const float* ga = A + (size_t)(bm0 + row) * DD + k0 + q * 4;
    const float* gb = B + (size_t)(bn0 + row) * DD + k0 + q * 4;
    #pragma unroll
    for (int p = 0; p < 4; p++) {
        CP_ASYNC16(da + (uint32_t)(p * 32 * SMSTRIDE * 4), ga + (size_t)p * 32 * DD);
        CP_ASYNC16(db + (uint32_t)(p * 32 * SMSTRIDE * 4), gb + (size_t)p * 32 * DD);
    }
}

template <int EPI, bool SYM>
__global__ __launch_bounds__(256, 2)
void gemm_bf16(const float* __restrict__ A, const float* __restrict__ B,
               float* __restrict__ C,
               const float* __restrict__ bias,
               const float* __restrict__ res) {
    extern __shared__ float sm[];
    const int t = threadIdx.x;
    const int lane = t & 31, wid = t >> 5;
    const int wm = (wid & 3) * 32;
    const int wn = (wid >> 2) * 64;

    int bm0, bn0;
    if (SYM) {
        int rem = blockIdx.x, i = 0;
        while (rem >= 16 - i) { rem -= 16 - i; i++; }
        bm0 = i * 128;
        bn0 = (i + rem) * 128;
    } else {
        bm0 = blockIdx.y * 128;
        bn0 = blockIdx.x * 128;
    }
    const uint32_t smbase = smem_u32(sm);

    float acc[2][8][4];
    #pragma unroll
    for (int i = 0; i < 2; i++)
        #pragma unroll
        for (int j = 0; j < 8; j++)
            #pragma unroll
            for (int q = 0; q < 4; q++) acc[i][j][q] = 0.f;

    load_stage(smbase, A, B, bm0, bn0, 0, 0, t);
    CP_COMMIT();

    const int g = lane >> 2;
    const int c2 = (lane & 3) * 2;
    const int rA = wm + g;
    const int rB = wn + g;

    for (int s = 0; s < 64; s++) {
        if (s < 63) {
            load_stage(smbase, A, B, bm0, bn0, (s + 1) * 32, (s + 1) & 1, t);
            CP_COMMIT();
            CP_WAIT(1);
        } else {
            CP_WAIT(0);
        }
        __syncthreads();

        const float* As = sm + (s & 1) * BUFW;
        const float* Bs = As + TILEW;
        #pragma unroll
        for (int slab = 0; slab < 2; slab++) {
            const int sk = slab * 16;
            uint32_t a[2][4], b[8][2];
            #pragma unroll
            for (int mt = 0; mt < 2; mt++) {
                const int base = (rA + mt * 16) * SMSTRIDE + sk + c2;
                a[mt][0] = pack2(*(const float2*)(As + base));
                a[mt][1] = pack2(*(const float2*)(As + base + 8 * SMSTRIDE));
                a[mt][2] = pack2(*(const float2*)(As + base + 8));
                a[mt][3] = pack2(*(const float2*)(As + base + 8 * SMSTRIDE + 8));
            }
            #pragma unroll
            for (int nt = 0; nt < 8; nt++) {
                const int base = (rB + nt * 8) * SMSTRIDE + sk + c2;
                b[nt][0] = pack2(*(const float2*)(Bs + base));
                b[nt][1] = pack2(*(const float2*)(Bs + base + 8));
            }
            #pragma unroll
            for (int mt = 0; mt < 2; mt++)
                #pragma unroll
                for (int nt = 0; nt < 8; nt++)
                    mma_bf16(acc[mt][nt], a[mt], b[nt]);
        }
        __syncthreads();
    }

    // ---- epilogue ----
    #pragma unroll
    for (int mt = 0; mt < 2; mt++) {
        const int row0 = bm0 + wm + mt * 16 + g;
        #pragma unroll
        for (int nt = 0; nt < 8; nt++) {
            const int col0 = bn0 + wn + nt * 8 + c2;
            float v0 = acc[mt][nt][0], v1 = acc[mt][nt][1];
            float v2 = acc[mt][nt][2], v3 = acc[mt][nt][3];
            if (EPI == 2) {
                float b0 = bias[col0], b1 = bias[col0 + 1];
                const float2 r0 = *(const float2*)&res[(size_t)row0 * DD + col0];
                const float2 r1 = *(const float2*)&res[(size_t)(row0 + 8) * DD + col0];
                v0 += b0 + r0.x; v1 += b1 + r0.y;
                v2 += b0 + r1.x; v3 += b1 + r1.y;
            }
            float2 o0 = {v0, v1}, o1 = {v2, v3};
            *(float2*)&C[(size_t)row0 * DD + col0] = o0;
            *(float2*)&C[(size_t)(row0 + 8) * DD + col0] = o1;
            if (SYM && bm0 != bn0) {
                C[(size_t)col0 * DD + row0] = v0;
                C[(size_t)(col0 + 1) * DD + row0] = v1;
                C[(size_t)col0 * DD + row0 + 8] = v2;
                C[(size_t)(col0 + 1) * DD + row0 + 8] = v3;
            }
        }
    }
}

// =====================================================================
// Head, split-K: part[ks][row][j] = sum_{k in ks} x[row,k]*W_all[j,k]
// =====================================================================
__global__ __launch_bounds__(256)
void head_partial(const float* __restrict__ x,
                  const float* __restrict__ Wc, const float* __restrict__ Wb,
                  float* __restrict__ part) {
    __shared__ float Wsm[48 * 64];
    __shared__ float xs[32 * 65];
    const int rb = blockIdx.x, ks = blockIdx.y;
    const int t = threadIdx.x;
    const int r = t & 31, jg = t >> 5;

    float acc[6] = {0.f, 0.f, 0.f, 0.f, 0.f, 0.f};

    for (int k0 = ks * 256; k0 < ks * 256 + 256; k0 += 64) {
        for (int i = t; i < 45 * 64; i += 256) {
            int j = i >> 6, k = i & 63;
            const float* w = (j < NCLS) ? (Wc + (size_t)j * DD)
                                        : (Wb + (size_t)(j - NCLS) * DD);
            Wsm[i] = w[k0 + k];
        }
        for (int i = t; i < 32 * 64; i += 256) {
            int rr = i >> 6, k = i & 63;
            xs[rr * 65 + k] = x[(size_t)(rb * 32 + rr) * DD + k0 + k];
        }
        __syncthreads();
        #pragma unroll 4
        for (int k = 0; k < 64; k++) {
            float xv = xs[r * 65 + k];
            #pragma unroll
            for (int u = 0; u < 6; u++) {
                int j = jg + 8 * u;
                if (j < 45) acc[u] += xv * Wsm[j * 64 + k];
            }
        }
        __syncthreads();
    }
    #pragma unroll
    for (int u = 0; u < 6; u++) {
        int j = jg + 8 * u;
        if (j < 45)
            part[((size_t)ks * NR + rb * 32 + r) * 45 + j] = acc[u];
    }
}

__global__ void head_reduce(const float* __restrict__ part,
                            const float* __restrict__ bc, const float* __restrict__ bb,
                            float* __restrict__ out) {
    int idx = blockIdx.x * 256 + threadIdx.x;
    if (idx >= NR * 45) return;
    int i = idx / 45, j = idx - i * 45;
    float s = 0.f;
    #pragma unroll
    for (int ks = 0; ks < 8; ks++) s += part[((size_t)ks * NR + i) * 45 + j];
    if (j < NCLS)
        out[(size_t)i * NCLS + j] = s + bc[j];
    else
        out[(size_t)NR * NCLS + (size_t)i * NBB + (j - NCLS)] = s + bb[j - NCLS];
}

// =====================================================================
extern "C" void kernel_launch(void* const* d_in, const int* in_sizes, int n_in,
                              void* d_out, int out_size) {
    const float* x  = (const float*)d_in[0];
    const float* Wt = (const float*)d_in[1];
    const float* bt = (const float*)d_in[2];
    const float* Wr = (const float*)d_in[3];
    const float* br = (const float*)d_in[4];
    const float* Wc = (const float*)d_in[5];
    const float* bc = (const float*)d_in[6];
    const float* Wb = (const float*)d_in[7];
    const float* bb = (const float*)d_in[8];
    float* out = (float*)d_out;

    float *A, *B, *M, *T, *AT, *XN;
    cudaGetSymbolAddress((void**)&A, g_A);
    cudaGetSymbolAddress((void**)&B, g_B);
    cudaGetSymbolAddress((void**)&M, g_M);
    cudaGetSymbolAddress((void**)&T, g_T);
    cudaGetSymbolAddress((void**)&AT, g_AT);
    cudaGetSymbolAddress((void**)&XN, g_N);

    const int SMEM = 2 * BUFW * 4;   // 81920 B
    cudaFuncSetAttribute(gemm_bf16<0, false>, cudaFuncAttributeMaxDynamicSharedMemorySize, SMEM);
    cudaFuncSetAttribute(gemm_bf16<2, false>, cudaFuncAttributeMaxDynamicSharedMemorySize, SMEM);
    cudaFuncSetAttribute(gemm_bf16<0, true>,  cudaFuncAttributeMaxDynamicSharedMemorySize, SMEM);

    dim3 gg(16, 16);

    avgpool_kernel<<<NR * DD / 128, 256>>>(x, A);

    // ---- layer 1 ----
    normalize_kernel<<<NR, 256>>>(A, XN);
    gemm_bf16<0, true><<<136, 256, SMEM>>>(XN, XN, M, nullptr, nullptr);   // cosine (sym)
    transpose_kernel<<<dim3(64, 64), dim3(32, 8)>>>(A, AT);
    gemm_bf16<0, false><<<gg, 256, SMEM>>>(M, AT, T, nullptr, nullptr);    // mat @ x
    softmax_kernel<<<NR, 256>>>(T);
    gemm_bf16<2, false><<<gg, 256, SMEM>>>(T, Wt, B, bt, A);               // @Wt^T+bt+x

    // ---- layer 2 ----
    normalize_kernel<<<NR, 256>>>(B, XN);
    gemm_bf16<0, true><<<136, 256, SMEM>>>(XN, XN, M, nullptr, nullptr);
    transpose_kernel<<<dim3(64, 64), dim3(32, 8)>>>(B, AT);
    gemm_bf16<0, false><<<gg, 256, SMEM>>>(M, AT, T, nullptr, nullptr);
    softmax_kernel<<<NR, 256>>>(T);
    gemm_bf16<2, false><<<gg, 256, SMEM>>>(T, Wr, A, br, B);               // @Wr^T+br+x2

    // ---- heads ----
    head_partial<<<dim3(64, 8), 256>>>(A, Wc, Wb, AT);
    head_reduce<<<(NR * 45 + 255) / 256, 256>>>(AT, bc, bb, out);
}

// round 5
// speedup vs baseline: 5.4366x; 1.4036x over previous
#include <cuda_runtime.h>
#include <cuda_bf16.h>
#include <math.h>
#include <stddef.h>
#include <stdint.h>

#define NR 2048
#define DD 2048
#define NCLS 9
#define NBB 36

// ---- scratch (device globals: allocation-free rule) ----
__device__ float g_A[NR * DD];                 // feat / x3 (fp32, residual)
__device__ float g_B[NR * DD];                 // x2 (fp32, residual)
__device__ float g_T[NR * DD];                 // mat@x (fp32) ; reused as head partials
__device__ __nv_bfloat16 g_XNb[NR * DD];       // normalized feats (bf16)
__device__ __nv_bfloat16 g_Mb[NR * NR];        // cosine matrix (bf16)
__device__ __nv_bfloat16 g_ATb[NR * DD];       // x^T (bf16)
__device__ __nv_bfloat16 g_Tb[NR * DD];        // softmax(mat@x) (bf16)
__device__ __nv_bfloat16 g_Wtb[DD * DD];       // Wt (bf16)
__device__ __nv_bfloat16 g_Wrb[DD * DD];       // Wr (bf16)

// =====================================================================
// helpers
// =====================================================================
__device__ __forceinline__ uint32_t smem_u32(const void* p) {
    uint32_t a;
    asm("{ .reg .u64 t; cvta.to.shared.u64 t, %1; cvt.u32.u64 %0, t; }"
        : "=r"(a) : "l"(p));
    return a;
}
__device__ __forceinline__ uint32_t pack2(float lo, float hi) {
    uint32_t r;
    asm("cvt.rn.bf16x2.f32 %0, %1, %2;" : "=r"(r) : "f"(hi), "f"(lo));
    return r;
}
#define CP_ASYNC16(dst, src) \
    asm volatile("cp.async.ca.shared.global [%0], [%1], 16;" :: "r"(dst), "l"(src) : "memory")
#define CP_COMMIT() asm volatile("cp.async.commit_group;" ::: "memory")
#define CP_WAIT(n)  asm volatile("cp.async.wait_group %0;" :: "n"(n) : "memory")
#define LDMATRIX_X4(r, addr)                                              \
    asm volatile("ldmatrix.sync.aligned.m8n8.x4.shared.b16 "              \
                 "{%0,%1,%2,%3}, [%4];"                                   \
                 : "=r"((r)[0]), "=r"((r)[1]), "=r"((r)[2]), "=r"((r)[3]) \
                 : "r"(addr))

__device__ __forceinline__ void mma_bf16(float* c, const uint32_t* a, const uint32_t* b) {
    asm volatile(
        "mma.sync.aligned.m16n8k16.row.col.f32.bf16.bf16.f32 "
        "{%0,%1,%2,%3}, {%4,%5,%6,%7}, {%8,%9}, {%0,%1,%2,%3};"
        : "+f"(c[0]), "+f"(c[1]), "+f"(c[2]), "+f"(c[3])
        : "r"(a[0]), "r"(a[1]), "r"(a[2]), "r"(a[3]), "r"(b[0]), "r"(b[1]));
}

// =====================================================================
// AvgPool2d(7,7): [N, D, 7, 7] -> [N, D]  (HBM-bound floor)
// =====================================================================
__global__ void avgpool_kernel(const float* __restrict__ x, float* __restrict__ out) {
    __shared__ float s[128 * 49];
    size_t block0 = (size_t)blockIdx.x * 128;
    const float4* src = reinterpret_cast<const float4*>(x + block0 * 49);
    float4* dst = reinterpret_cast<float4*>(s);
    for (int i = threadIdx.x; i < 128 * 49 / 4; i += 256) dst[i] = src[i];
    __syncthreads();
    if (threadIdx.x < 128) {
        float sum = 0.f;
        #pragma unroll
        for (int k = 0; k < 49; k++) sum += s[threadIdx.x * 49 + k];
        out[block0 + threadIdx.x] = sum * (1.f / 49.f);
    }
}

// =====================================================================
// fp32 -> bf16 convert (weights), 8 elems/thread
// =====================================================================
__global__ void f2b_kernel(const float* __restrict__ in, __nv_bfloat16* __restrict__ out) {
    size_t i = ((size_t)blockIdx.x * 256 + threadIdx.x) * 8;
    const float4 a = *(const float4*)(in + i);
    const float4 b = *(const float4*)(in + i + 4);
    uint4 o;
    o.x = pack2(a.x, a.y); o.y = pack2(a.z, a.w);
    o.z = pack2(b.x, b.y); o.w = pack2(b.z, b.w);
    *(uint4*)(out + i) = o;
}

// =====================================================================
// Row L2-normalize -> bf16: xn[i,:] = x[i,:] / max(||x||, 1e-8)
// =====================================================================
__global__ void normalize_kernel(const float* __restrict__ f, __nv_bfloat16* __restrict__ fn) {
    __shared__ float red[256];
    int row = blockIdx.x, t = threadIdx.x;
    const float4* p = reinterpret_cast<const float4*>(f + (size_t)row * DD);
    float4 v0 = p[2 * t], v1 = p[2 * t + 1];
    float s = v0.x * v0.x + v0.y * v0.y + v0.z * v0.z + v0.w * v0.w
            + v1.x * v1.x + v1.y * v1.y + v1.z * v1.z + v1.w * v1.w;
    red[t] = s;
    __syncthreads();
    for (int o = 128; o; o >>= 1) {
        if (t < o) red[t] += red[t + o];
        __syncthreads();
    }
    float inv = 1.f / fmaxf(sqrtf(red[0]), 1e-8f);
    uint4 o;
    o.x = pack2(v0.x * inv, v0.y * inv);
    o.y = pack2(v0.z * inv, v0.w * inv);
    o.z = pack2(v1.x * inv, v1.y * inv);
    o.w = pack2(v1.z * inv, v1.w * inv);
    *(uint4*)(fn + (size_t)row * DD + t * 8) = o;
}

// =====================================================================
// Row softmax: read fp32 [NR,2048], write bf16
// =====================================================================
__global__ void softmax_kernel(const float* __restrict__ in, __nv_bfloat16* __restrict__ outb) {
    __shared__ float red[256];
    int row = blockIdx.x, t = threadIdx.x;
    const float4* p = reinterpret_cast<const float4*>(in + (size_t)row * NR);
    float4 u0 = p[2 * t], u1 = p[2 * t + 1];
    float v[8] = {u0.x, u0.y, u0.z, u0.w, u1.x, u1.y, u1.z, u1.w};
    float mx = v[0];
    #pragma unroll
    for (int i = 1; i < 8; i++) mx = fmaxf(mx, v[i]);
    red[t] = mx;
    __syncthreads();
    for (int o = 128; o; o >>= 1) {
        if (t < o) red[t] = fmaxf(red[t], red[t + o]);
        __syncthreads();
    }
    mx = red[0];
    __syncthreads();
    float s = 0.f;
    #pragma unroll
    for (int i = 0; i < 8; i++) {
        v[i] = __expf(v[i] - mx);
        s += v[i];
    }
    red[t] = s;
    __syncthreads();
    for (int o = 128; o; o >>= 1) {
        if (t < o) red[t] += red[t + o];
        __syncthreads();
    }
    float inv = 1.f / red[0];
    uint4 o;
    o.x = pack2(v[0] * inv, v[1] * inv);
    o.y = pack2(v[2] * inv, v[3] * inv);
    o.z = pack2(v[4] * inv, v[5] * inv);
    o.w = pack2(v[6] * inv, v[7] * inv);
    *(uint4*)(outb + (size_t)row * NR + t * 8) = o;
}

// =====================================================================
// 32x32 tiled transpose: out(bf16) = in(fp32)^T
// =====================================================================
__global__ void transpose_kernel(const float* __restrict__ in, __nv_bfloat16* __restrict__ out) {
    __shared__ float tile[32][33];
    int x = blockIdx.x * 32 + threadIdx.x;
    int y = blockIdx.y * 32 + threadIdx.y;
    #pragma unroll
    for (int j = 0; j < 32; j += 8)
        tile[threadIdx.y + j][threadIdx.x] = in[(size_t)(y + j) * DD + x];
    __syncthreads();
    x = blockIdx.y * 32 + threadIdx.x;
    y = blockIdx.x * 32 + threadIdx.y;
    #pragma unroll
    for (int j = 0; j < 32; j += 8)
        out[(size_t)(y + j) * DD + x] = __float2bfloat16_rn(tile[threadIdx.x][threadIdx.y + j]);
}

// =====================================================================
// bf16 NT GEMM via ldmatrix + mma.m16n8k16: C[m,n] = sum_k A[m,k]*B[n,k]
// 128x128 CTA tile, 256 thr (8 warps @ 32x64), BK=64, cp.async dbl-buf.
// bf16 smem, 128B rows, SW128 swizzle (consistent cp.async/ldmatrix).
// EPI: 0 plain | 2 (+bias[c]+res[r,c]).  SYM: triangular grid + mirror.
// OUTBF: write C as bf16 (row-major [2048]).
// =====================================================================
#define STG 16384   // bytes per operand per stage (128 rows * 128B)

__device__ __forceinline__ void load_stage(uint32_t sb32,
                                           const __nv_bfloat16* A, const __nv_bfloat16* B,
                                           int bm0, int bn0, int k0, int buf, int t) {
    const int ch = t & 7;        // 16B chunk within 128B row
    const int r0 = t >> 3;       // 0..31
    const uint32_t abase = sb32 + (uint32_t)buf * (2 * STG);
    #pragma unroll
    for (int p = 0; p < 4; p++) {
        const int row = r0 + p * 32;
        uint32_t o = (uint32_t)row * 128 + ch * 16;
        uint32_t sw = o ^ ((o >> 3) & 0x70);
        CP_ASYNC16(abase + sw, A + (size_t)(bm0 + row) * DD + k0 + ch * 8);
        CP_ASYNC16(abase + STG + sw, B + (size_t)(bn0 + row) * DD + k0 + ch * 8);
    }
}

template <int EPI, bool SYM, bool OUTBF>
__global__ __launch_bounds__(256, 2)
void gemm_bf16(const __nv_bfloat16* __restrict__ A, const __nv_bfloat16* __restrict__ B,
               void* __restrict__ Cv,
               const float* __restrict__ bias,
               const float* __restrict__ res) {
    extern __shared__ char dynsm[];
    char* sb = (char*)(((uintptr_t)dynsm + 1023) & ~(uintptr_t)1023);
    const uint32_t sb32 = smem_u32(sb);

    const int t = threadIdx.x;
    const int lane = t & 31, wid = t >> 5;
    const int wm = (wid & 3) * 32;
    const int wn = (wid >> 2) * 64;

    int bm0, bn0;
    if (SYM) {
        int rem = blockIdx.x, i = 0;
        while (rem >= 16 - i) { rem -= 16 - i; i++; }
        bm0 = i * 128;
        bn0 = (i + rem) * 128;
    } else {
        bm0 = blockIdx.y * 128;
        bn0 = blockIdx.x * 128;
    }

    float acc[2][8][4];
    #pragma unroll
    for (int i = 0; i < 2; i++)
        #pragma unroll
        for (int j = 0; j < 8; j++)
            #pragma unroll
            for (int q = 0; q < 4; q++) acc[i][j][q] = 0.f;

    load_stage(sb32, A, B, bm0, bn0, 0, 0, t);
    CP_COMMIT();

    // ldmatrix lane addressing
    const int a_row_l = lane & 15;
    const int a_kb = (lane >> 4) * 16;            // 0 or 16 bytes
    const int b_row_l = ((lane >> 4) << 3) + (lane & 7);
    const int b_kb = ((lane >> 3) & 1) * 16;

    for (int s = 0; s < 32; s++) {
        if (s < 31) {
            load_stage(sb32, A, B, bm0, bn0, (s + 1) * 64, (s + 1) & 1, t);
            CP_COMMIT();
            CP_WAIT(1);
        } else {
            CP_WAIT(0);
        }
        __syncthreads();

        const uint32_t aB = sb32 + (uint32_t)(s & 1) * (2 * STG);
        const uint32_t bB = aB + STG;
        #pragma unroll
        for (int kk = 0; kk < 4; kk++) {
            const int kb = kk * 32;               // 16 k-elems = 32B
            uint32_t af[2][4], bf[4][4];
            #pragma unroll
            for (int mt = 0; mt < 2; mt++) {
                uint32_t o = (uint32_t)(wm + mt * 16 + a_row_l) * 128 + kb + a_kb;
                LDMATRIX_X4(af[mt], aB + (o ^ ((o >> 3) & 0x70)));
            }
            #pragma unroll
            for (int nt2 = 0; nt2 < 4; nt2++) {
                uint32_t o = (uint32_t)(wn + nt2 * 16 + b_row_l) * 128 + kb + b_kb;
                LDMATRIX_X4(bf[nt2], bB + (o ^ ((o >> 3) & 0x70)));
            }
            #pragma unroll
            for (int mt = 0; mt < 2; mt++)
                #pragma unroll
                for (int nt2 = 0; nt2 < 4; nt2++) {
                    mma_bf16(acc[mt][nt2 * 2 + 0], af[mt], &bf[nt2][0]);
                    mma_bf16(acc[mt][nt2 * 2 + 1], af[mt], &bf[nt2][2]);
                }
        }
        __syncthreads();
    }

    // ---- epilogue ----
    const int g = lane >> 2;
    const int c2 = (lane & 3) * 2;
    float* Cf = (float*)Cv;
    __nv_bfloat16* Cb = (__nv_bfloat16*)Cv;

    #pragma unroll
    for (int mt = 0; mt < 2; mt++) {
        const int row0 = bm0 + wm + mt * 16 + g;
        #pragma unroll
        for (int nt = 0; nt < 8; nt++) {
            const int col0 = bn0 + wn + nt * 8 + c2;
            float v0 = acc[mt][nt][0], v1 = acc[mt][nt][1];
            float v2 = acc[mt][nt][2], v3 = acc[mt][nt][3];
            if (EPI == 2) {
                float b0 = bias[col0], b1 = bias[col0 + 1];
                const float2 r0 = *(const float2*)&res[(size_t)row0 * DD + col0];
                const float2 r1 = *(const float2*)&res[(size_t)(row0 + 8) * DD + col0];
                v0 += b0 + r0.x; v1 += b1 + r0.y;
                v2 += b0 + r1.x; v3 += b1 + r1.y;
            }
            if (OUTBF) {
                *(uint32_t*)&Cb[(size_t)row0 * DD + col0] = pack2(v0, v1);
                *(uint32_t*)&Cb[(size_t)(row0 + 8) * DD + col0] = pack2(v2, v3);
                if (SYM && bm0 != bn0) {
                    Cb[(size_t)col0 * DD + row0] = __float2bfloat16_rn(v0);
                    Cb[(size_t)(col0 + 1) * DD + row0] = __float2bfloat16_rn(v1);
                    Cb[(size_t)col0 * DD + row0 + 8] = __float2bfloat16_rn(v2);
                    Cb[(size_t)(col0 + 1) * DD + row0 + 8] = __float2bfloat16_rn(v3);
                }
            } else {
                float2 o0 = {v0, v1}, o1 = {v2, v3};
                *(float2*)&Cf[(size_t)row0 * DD + col0] = o0;
                *(float2*)&Cf[(size_t)(row0 + 8) * DD + col0] = o1;
            }
        }
    }
}

// =====================================================================
// Head, split-K: part[ks][row][j] = sum_{k in ks} x[row,k]*W_all[j,k]
// =====================================================================
__global__ __launch_bounds__(256)
void head_partial(const float* __restrict__ x,
                  const float* __restrict__ Wc, const float* __restrict__ Wb,
                  float* __restrict__ part) {
    __shared__ float Wsm[48 * 64];
    __shared__ float xs[32 * 65];
    const int rb = blockIdx.x, ks = blockIdx.y;
    const int t = threadIdx.x;
    const int r = t & 31, jg = t >> 5;

    float acc[6] = {0.f, 0.f, 0.f, 0.f, 0.f, 0.f};

    for (int k0 = ks * 256; k0 < ks * 256 + 256; k0 += 64) {
        for (int i = t; i < 45 * 64; i += 256) {
            int j = i >> 6, k = i & 63;
            const float* w = (j < NCLS) ? (Wc + (size_t)j * DD)
                                        : (Wb + (size_t)(j - NCLS) * DD);
            Wsm[i] = w[k0 + k];
        }
        for (int i = t; i < 32 * 64; i += 256) {
            int rr = i >> 6, k = i & 63;
            xs[rr * 65 + k] = x[(size_t)(rb * 32 + rr) * DD + k0 + k];
        }
        __syncthreads();
        #pragma unroll 4
        for (int k = 0; k < 64; k++) {
            float xv = xs[r * 65 + k];
            #pragma unroll
            for (int u = 0; u < 6; u++) {
                int j = jg + 8 * u;
                if (j < 45) acc[u] += xv * Wsm[j * 64 + k];
            }
        }
        __syncthreads();
    }
    #pragma unroll
    for (int u = 0; u < 6; u++) {
        int j = jg + 8 * u;
        if (j < 45)
            part[((size_t)ks * NR + rb * 32 + r) * 45 + j] = acc[u];
    }
}

__global__ void head_reduce(const float* __restrict__ part,
                            const float* __restrict__ bc, const float* __restrict__ bb,
                            float* __restrict__ out) {
    int idx = blockIdx.x * 256 + threadIdx.x;
    if (idx >= NR * 45) return;
    int i = idx / 45, j = idx - i * 45;
    float s = 0.f;
    #pragma unroll
    for (int ks = 0; ks < 8; ks++) s += part[((size_t)ks * NR + i) * 45 + j];
    if (j < NCLS)
        out[(size_t)i * NCLS + j] = s + bc[j];
    else
        out[(size_t)NR * NCLS + (size_t)i * NBB + (j - NCLS)] = s + bb[j - NCLS];
}

// =====================================================================
extern "C" void kernel_launch(void* const* d_in, const int* in_sizes, int n_in,
                              void* d_out, int out_size) {
    const float* x  = (const float*)d_in[0];
    const float* Wt = (const float*)d_in[1];
    const float* bt = (const float*)d_in[2];
    const float* Wr = (const float*)d_in[3];
    const float* br = (const float*)d_in[4];
    const float* Wc = (const float*)d_in[5];
    const float* bc = (const float*)d_in[6];
    const float* Wb = (const float*)d_in[7];
    const float* bb = (const float*)d_in[8];
    float* out = (float*)d_out;

    float *A, *B, *T;
    __nv_bfloat16 *XNb, *Mb, *ATb, *Tb, *Wtb, *Wrb;
    cudaGetSymbolAddress((void**)&A, g_A);
    cudaGetSymbolAddress((void**)&B, g_B);
    cudaGetSymbolAddress((void**)&T, g_T);
    cudaGetSymbolAddress((void**)&XNb, g_XNb);
    cudaGetSymbolAddress((void**)&Mb, g_Mb);
    cudaGetSymbolAddress((void**)&ATb, g_ATb);
    cudaGetSymbolAddress((void**)&Tb, g_Tb);
    cudaGetSymbolAddress((void**)&Wtb, g_Wtb);
    cudaGetSymbolAddress((void**)&Wrb, g_Wrb);

    const int SMEM = 4 * STG + 1024;   // 66560 B
    cudaFuncSetAttribute(gemm_bf16<0, false, false>, cudaFuncAttributeMaxDynamicSharedMemorySize, SMEM);
    cudaFuncSetAttribute(gemm_bf16<2, false, false>, cudaFuncAttributeMaxDynamicSharedMemorySize, SMEM);
    cudaFuncSetAttribute(gemm_bf16<0, true, true>,   cudaFuncAttributeMaxDynamicSharedMemorySize, SMEM);

    dim3 gg(16, 16);

    avgpool_kernel<<<NR * DD / 128, 256>>>(x, A);
    f2b_kernel<<<DD * DD / 2048, 256>>>(Wt, Wtb);
    f2b_kernel<<<DD * DD / 2048, 256>>>(Wr, Wrb);

    // ---- layer 1 ----
    normalize_kernel<<<NR, 256>>>(A, XNb);
    gemm_bf16<0, true, true><<<136, 256, SMEM>>>(XNb, XNb, Mb, nullptr, nullptr);   // cosine
    transpose_kernel<<<dim3(64, 64), dim3(32, 8)>>>(A, ATb);
    gemm_bf16<0, false, false><<<gg, 256, SMEM>>>(Mb, ATb, T, nullptr, nullptr);    // mat @ x
    softmax_kernel<<<NR, 256>>>(T, Tb);
    gemm_bf16<2, false, false><<<gg, 256, SMEM>>>(Tb, Wtb, B, bt, A);               // @Wt^T+bt+x

    // ---- layer 2 ----
    normalize_kernel<<<NR, 256>>>(B, XNb);
    gemm_bf16<0, true, true><<<136, 256, SMEM>>>(XNb, XNb, Mb, nullptr, nullptr);
    transpose_kernel<<<dim3(64, 64), dim3(32, 8)>>>(B, ATb);
    gemm_bf16<0, false, false><<<gg, 256, SMEM>>>(Mb, ATb, T, nullptr, nullptr);
    softmax_kernel<<<NR, 256>>>(T, Tb);
    gemm_bf16<2, false, false><<<gg, 256, SMEM>>>(Tb, Wrb, A, br, B);               // @Wr^T+br+x2

    // ---- heads (partials into T scratch) ----
    head_partial<<<dim3(64, 8), 256>>>(A, Wc, Wb, T);
    head_reduce<<<(NR * 45 + 255) / 256, 256>>>(T, bc, bb, out);
}